// round 5
// baseline (speedup 1.0000x reference)
#include <cuda_runtime.h>

#define NN   100000
#define EE   20000
#define NNZV 1000000
#define DIM  128

// ---- scratch (device globals; total ~20.3 MB) ----
__device__ int   g_ecnt[EE];
__device__ int   g_ncnt[NN];
__device__ int   g_eoff[EE + 1];
__device__ int   g_noff[NN + 1];
__device__ int   g_ecur[EE];
__device__ int   g_ncur[NN];
__device__ int   g_pe[64];          // per-block partials (edges: 20 blocks)
__device__ int   g_pn[128];         // (nodes: 98 blocks)
__device__ int   g_erows[NNZV];     // CSR by edge: row index per slot  (4 MB)
__device__ int   g_ncols[NNZV];     // CSC by node: col index per slot  (4 MB)
__device__ float g_m[EE * DIM];     // 10.24 MB hyperedge features (de^-1 folded)
__device__ float g_dvis[NN];        // dv^-1/2
__device__ float g_deinv[EE];       // de^-1

// ---- 1) zero counters + precompute scales ----
__global__ void init_kernel(const float* __restrict__ dv,
                            const float* __restrict__ de) {
    int tid = blockIdx.x * blockDim.x + threadIdx.x;
    int stride = gridDim.x * blockDim.x;
    for (int i = tid; i < NN; i += stride) {
        g_ncnt[i] = 0;
        g_dvis[i] = rsqrtf(__ldg(dv + i));
    }
    for (int i = tid; i < EE; i += stride) {
        g_ecnt[i] = 0;
        g_deinv[i] = 1.0f / __ldg(de + i);
    }
}

// ---- 2) histogram degrees ----
__global__ void count_kernel(const int* __restrict__ rows,
                             const int* __restrict__ cols) {
    int tid = blockIdx.x * blockDim.x + threadIdx.x;
    int stride = gridDim.x * blockDim.x;
    for (int i = tid; i < NNZV; i += stride) {
        atomicAdd(&g_ecnt[__ldg(cols + i)], 1);
        atomicAdd(&g_ncnt[__ldg(rows + i)], 1);
    }
}

// ---- 3) block-level exclusive scans (device-global refs ONLY — no host
//         pointers to __device__ symbols, that was the rounds-2..4 bug) ----
__device__ __forceinline__ void block_scan_body(const int* cnt, int* off,
                                                int* partial, int len) {
    __shared__ int s[1024];
    int tid = threadIdx.x;
    int i = blockIdx.x * 1024 + tid;
    int v = (i < len) ? cnt[i] : 0;
    s[tid] = v;
    for (int d = 1; d < 1024; d <<= 1) {
        __syncthreads();
        int t = (tid >= d) ? s[tid - d] : 0;
        __syncthreads();
        s[tid] += t;
    }
    __syncthreads();
    if (i < len) off[i] = s[tid] - v;           // exclusive within block
    if (tid == 1023) partial[blockIdx.x] = s[1023];
}

__global__ void scanA_edges_kernel() { block_scan_body(g_ecnt, g_eoff, g_pe, EE); }
__global__ void scanA_nodes_kernel() { block_scan_body(g_ncnt, g_noff, g_pn, NN); }

// ---- 4) scan the partials (tiny) ----
__global__ void scanB_kernel(int nbe, int nbn) {
    if (threadIdx.x == 0) {
        int run = 0;
        for (int b = 0; b < nbe; b++) { int t = g_pe[b]; g_pe[b] = run; run += t; }
    }
    if (threadIdx.x == 1) {
        int run = 0;
        for (int b = 0; b < nbn; b++) { int t = g_pn[b]; g_pn[b] = run; run += t; }
    }
}

// ---- 5) finalize offsets + init fill cursors ----
__global__ void scanC_kernel() {
    int tid = blockIdx.x * blockDim.x + threadIdx.x;
    int stride = gridDim.x * blockDim.x;
    for (int i = tid; i < EE; i += stride) {
        int o = g_eoff[i] + g_pe[i >> 10];
        g_eoff[i] = o;
        g_ecur[i] = o;
    }
    for (int i = tid; i < NN; i += stride) {
        int o = g_noff[i] + g_pn[i >> 10];
        g_noff[i] = o;
        g_ncur[i] = o;
    }
    if (tid == 0) { g_eoff[EE] = NNZV; g_noff[NN] = NNZV; }
}

// ---- 6) fill buckets ----
__global__ void fill_kernel(const int* __restrict__ rows,
                            const int* __restrict__ cols) {
    int tid = blockIdx.x * blockDim.x + threadIdx.x;
    int stride = gridDim.x * blockDim.x;
    for (int i = tid; i < NNZV; i += stride) {
        int r = __ldg(rows + i);
        int c = __ldg(cols + i);
        int p = atomicAdd(&g_ecur[c], 1);
        g_erows[p] = r;
        int q = atomicAdd(&g_ncur[r], 1);
        g_ncols[q] = c;
    }
}

// ---- 7) m[e] = de^-1 * sum_{r in e} dv^-1/2[r] * X[r]   (block per edge) ----
__global__ __launch_bounds__(128)
void phase1_kernel(const float* __restrict__ X) {
    int e = blockIdx.x;
    int j = threadIdx.x;
    int i = g_eoff[e], end = g_eoff[e + 1];
    float acc = 0.f;
    for (; i + 4 <= end; i += 4) {
        int r0 = g_erows[i], r1 = g_erows[i + 1];
        int r2 = g_erows[i + 2], r3 = g_erows[i + 3];
        float a0 = g_dvis[r0] * __ldg(X + r0 * DIM + j);
        float a1 = g_dvis[r1] * __ldg(X + r1 * DIM + j);
        float a2 = g_dvis[r2] * __ldg(X + r2 * DIM + j);
        float a3 = g_dvis[r3] * __ldg(X + r3 * DIM + j);
        acc += (a0 + a1) + (a2 + a3);
    }
    for (; i < end; i++) {
        int r = g_erows[i];
        acc += g_dvis[r] * __ldg(X + r * DIM + j);
    }
    g_m[e * DIM + j] = acc * g_deinv[e];
}

// ---- 8) fused: y-tile gather (phase2) + GEMM.  BM=64, 256 threads ----
#define YT_STRIDE 68
__global__ __launch_bounds__(256, 2)
void gemm_fused_kernel(const float* __restrict__ W, float* __restrict__ out) {
    extern __shared__ float smem[];
    float* Yt = smem;                       // [DIM][YT_STRIDE] k-major
    float* Ws = smem + DIM * YT_STRIDE;     // [DIM][DIM] row-major

    int tid = threadIdx.x;
    int block_row = blockIdx.x * 64;

    // Stage W (coalesced)
    for (int i = tid; i < DIM * (DIM / 4); i += 256) {
        int r = i >> 5, c4 = i & 31;
        float4 v = __ldg(reinterpret_cast<const float4*>(W) + r * (DIM / 4) + c4);
        *reinterpret_cast<float4*>(&Ws[r * DIM + c4 * 4]) = v;
    }

    // Gather y rows directly into Yt: warp = 32 consecutive j's of one node,
    // so each edge read is a coalesced 128B segment of g_m (L2-resident).
    {
        int j = tid & 127;
        int half = tid >> 7;
        for (int it = 0; it < 32; it++) {
            int rl = it * 2 + half;
            int n = block_row + rl;
            float acc = 0.f;
            if (n < NN) {
                int i = g_noff[n], end = g_noff[n + 1];
                for (; i + 4 <= end; i += 4) {
                    int c0 = g_ncols[i], c1 = g_ncols[i + 1];
                    int c2 = g_ncols[i + 2], c3 = g_ncols[i + 3];
                    float a0 = g_m[c0 * DIM + j];
                    float a1 = g_m[c1 * DIM + j];
                    float a2 = g_m[c2 * DIM + j];
                    float a3 = g_m[c3 * DIM + j];
                    acc += (a0 + a1) + (a2 + a3);
                }
                for (; i < end; i++) acc += g_m[g_ncols[i] * DIM + j];
                acc *= g_dvis[n];
            }
            Yt[j * YT_STRIDE + rl] = acc;
        }
    }
    __syncthreads();

    int tx = tid & 15;    // 8 output cols
    int ty = tid >> 4;    // 4 output rows

    float acc[4][8];
#pragma unroll
    for (int i = 0; i < 4; i++)
#pragma unroll
        for (int j = 0; j < 8; j++) acc[i][j] = 0.f;

#pragma unroll 4
    for (int k = 0; k < DIM; k++) {
        float yf[4], wf[8];
        *reinterpret_cast<float4*>(&yf[0]) = *reinterpret_cast<float4*>(&Yt[k * YT_STRIDE + ty * 4]);
        *reinterpret_cast<float4*>(&wf[0]) = *reinterpret_cast<float4*>(&Ws[k * DIM + tx * 8]);
        *reinterpret_cast<float4*>(&wf[4]) = *reinterpret_cast<float4*>(&Ws[k * DIM + tx * 8 + 4]);
#pragma unroll
        for (int i = 0; i < 4; i++)
#pragma unroll
            for (int j = 0; j < 8; j++)
                acc[i][j] += yf[i] * wf[j];
    }

#pragma unroll
    for (int i = 0; i < 4; i++) {
        int n = block_row + ty * 4 + i;
        if (n < NN) {
            float4 lo = make_float4(acc[i][0], acc[i][1], acc[i][2], acc[i][3]);
            float4 hi = make_float4(acc[i][4], acc[i][5], acc[i][6], acc[i][7]);
            *reinterpret_cast<float4*>(&out[n * DIM + tx * 8])     = lo;
            *reinterpret_cast<float4*>(&out[n * DIM + tx * 8 + 4]) = hi;
        }
    }
}

extern "C" void kernel_launch(void* const* d_in, const int* in_sizes, int n_in,
                              void* d_out, int out_size) {
    const float* X    = (const float*)d_in[0];
    const int*   rows = (const int*)  d_in[1];
    const int*   cols = (const int*)  d_in[2];
    const float* dv   = (const float*)d_in[3];
    const float* de   = (const float*)d_in[4];
    const float* W    = (const float*)d_in[5];
    float*       out  = (float*)d_out;

    const int NBE = (EE + 1023) / 1024;   // 20
    const int NBN = (NN + 1023) / 1024;   // 98

    init_kernel<<<512, 256>>>(dv, de);
    count_kernel<<<2048, 256>>>(rows, cols);
    scanA_edges_kernel<<<NBE, 1024>>>();
    scanA_nodes_kernel<<<NBN, 1024>>>();
    scanB_kernel<<<1, 32>>>(NBE, NBN);
    scanC_kernel<<<512, 256>>>();
    fill_kernel<<<2048, 256>>>(rows, cols);
    phase1_kernel<<<EE, 128>>>(X);

    const size_t GEMM_SMEM = (DIM * YT_STRIDE + DIM * DIM) * sizeof(float); // ~98 KB
    cudaFuncSetAttribute(gemm_fused_kernel, cudaFuncAttributeMaxDynamicSharedMemorySize,
                         (int)GEMM_SMEM);
    gemm_fused_kernel<<<(NN + 63) / 64, 256, GEMM_SMEM>>>(W, out);
}

// round 6
// speedup vs baseline: 1.7087x; 1.7087x over previous
#include <cuda_runtime.h>

#define NN   100000
#define EE   20000
#define NNZV 1000000
#define DIM  128

// ---- scratch: ~20.7 MB of device globals ----
__device__ float g_m[EE * DIM];    // 10.24 MB  hyperedge accumulator (raw sums)
__device__ float g_m2[EE * DIM];   // 10.24 MB  (de^-1 * m) @ W

__device__ __forceinline__ void red4(float* p, float4 v) {
    asm volatile("red.global.add.v4.f32 [%0], {%1,%2,%3,%4};"
                 :: "l"(p), "f"(v.x), "f"(v.y), "f"(v.z), "f"(v.w) : "memory");
}

// ---- 1) zero m and out ----
__global__ void zero_kernel(float* __restrict__ out) {
    int tid = blockIdx.x * blockDim.x + threadIdx.x;
    int stride = gridDim.x * blockDim.x;
    float4* m4 = reinterpret_cast<float4*>(g_m);
    float4* o4 = reinterpret_cast<float4*>(out);
    const int M4 = EE * DIM / 4;
    const int O4 = NN * DIM / 4;
    float4 z = make_float4(0.f, 0.f, 0.f, 0.f);
    for (int i = tid; i < M4; i += stride) m4[i] = z;
    for (int i = tid; i < O4; i += stride) o4[i] = z;
}

// ---- 2) m[c] += dv[r]^-1/2 * X[r]   (warp per entry, float4 per lane; R1-proven) ----
__global__ void scatter1_kernel(const float* __restrict__ X,
                                const int*   __restrict__ rows,
                                const int*   __restrict__ cols,
                                const float* __restrict__ dv) {
    int w = (blockIdx.x * blockDim.x + threadIdx.x) >> 5;
    if (w >= NNZV) return;
    int lane = threadIdx.x & 31;
    int r = __ldg(rows + w);
    int c = __ldg(cols + w);
    float s = rsqrtf(__ldg(dv + r));
    float4 v = __ldg(reinterpret_cast<const float4*>(X) + r * (DIM / 4) + lane);
    v.x *= s; v.y *= s; v.z *= s; v.w *= s;
    red4(g_m + c * DIM + lane * 4, v);
}

// ---- 3) M2 = (de^-1 ⊙ m) @ W    (E=20K rows; BM=64, 2 CTA/SM) ----
#define YT_STRIDE 68
__global__ __launch_bounds__(256, 2)
void gemmE_kernel(const float* __restrict__ de, const float* __restrict__ W) {
    extern __shared__ float smem[];
    float* Yt = smem;                       // [DIM][YT_STRIDE] k-major: Yt[k*68 + r]
    float* Ws = smem + DIM * YT_STRIDE;     // [DIM][DIM] row-major

    int tid = threadIdx.x;
    int block_row = blockIdx.x * 64;

    // Stage W (coalesced)
    for (int i = tid; i < DIM * (DIM / 4); i += 256) {
        int r = i >> 5, c4 = i & 31;
        float4 v = __ldg(reinterpret_cast<const float4*>(W) + r * (DIM / 4) + c4);
        *reinterpret_cast<float4*>(&Ws[r * DIM + c4 * 4]) = v;
    }
    // Stage m tile k-major with de^-1 folded in
    for (int i = tid; i < (DIM / 4) * 64; i += 256) {
        int r = i & 63, c4 = i >> 6;
        int e = block_row + r;
        float4 v = make_float4(0.f, 0.f, 0.f, 0.f);
        if (e < EE) {
            float s = 1.0f / __ldg(de + e);
            v = *(reinterpret_cast<const float4*>(g_m) + e * (DIM / 4) + c4);
            v.x *= s; v.y *= s; v.z *= s; v.w *= s;
        }
        Yt[(c4 * 4 + 0) * YT_STRIDE + r] = v.x;
        Yt[(c4 * 4 + 1) * YT_STRIDE + r] = v.y;
        Yt[(c4 * 4 + 2) * YT_STRIDE + r] = v.z;
        Yt[(c4 * 4 + 3) * YT_STRIDE + r] = v.w;
    }
    __syncthreads();

    int tx = tid & 15;    // 8 output cols
    int ty = tid >> 4;    // 4 output rows

    float acc[4][8];
#pragma unroll
    for (int i = 0; i < 4; i++)
#pragma unroll
        for (int j = 0; j < 8; j++) acc[i][j] = 0.f;

#pragma unroll 4
    for (int k = 0; k < DIM; k++) {
        float yf[4], wf[8];
        *reinterpret_cast<float4*>(&yf[0]) = *reinterpret_cast<float4*>(&Yt[k * YT_STRIDE + ty * 4]);
        *reinterpret_cast<float4*>(&wf[0]) = *reinterpret_cast<float4*>(&Ws[k * DIM + tx * 8]);
        *reinterpret_cast<float4*>(&wf[4]) = *reinterpret_cast<float4*>(&Ws[k * DIM + tx * 8 + 4]);
#pragma unroll
        for (int i = 0; i < 4; i++)
#pragma unroll
            for (int j = 0; j < 8; j++)
                acc[i][j] += yf[i] * wf[j];
    }

#pragma unroll
    for (int i = 0; i < 4; i++) {
        int e = block_row + ty * 4 + i;
        if (e < EE) {
            float4 lo = make_float4(acc[i][0], acc[i][1], acc[i][2], acc[i][3]);
            float4 hi = make_float4(acc[i][4], acc[i][5], acc[i][6], acc[i][7]);
            *reinterpret_cast<float4*>(&g_m2[e * DIM + tx * 8])     = lo;
            *reinterpret_cast<float4*>(&g_m2[e * DIM + tx * 8 + 4]) = hi;
        }
    }
}

// ---- 4) out[r] += dv[r]^-1/2 * M2[c]   (same proven scatter shape) ----
__global__ void scatter3_kernel(const int*   __restrict__ rows,
                                const int*   __restrict__ cols,
                                const float* __restrict__ dv,
                                float*       __restrict__ out) {
    int w = (blockIdx.x * blockDim.x + threadIdx.x) >> 5;
    if (w >= NNZV) return;
    int lane = threadIdx.x & 31;
    int r = __ldg(rows + w);
    int c = __ldg(cols + w);
    float s = rsqrtf(__ldg(dv + r));
    float4 v = *(reinterpret_cast<const float4*>(g_m2) + c * (DIM / 4) + lane);
    v.x *= s; v.y *= s; v.z *= s; v.w *= s;
    red4(out + r * DIM + lane * 4, v);
}

extern "C" void kernel_launch(void* const* d_in, const int* in_sizes, int n_in,
                              void* d_out, int out_size) {
    const float* X    = (const float*)d_in[0];
    const int*   rows = (const int*)  d_in[1];
    const int*   cols = (const int*)  d_in[2];
    const float* dv   = (const float*)d_in[3];
    const float* de   = (const float*)d_in[4];
    const float* W    = (const float*)d_in[5];
    float*       out  = (float*)d_out;

    zero_kernel<<<2048, 256>>>(out);

    long long total_threads = (long long)NNZV * 32;
    int blocks = (int)((total_threads + 255) / 256);
    scatter1_kernel<<<blocks, 256>>>(X, rows, cols, dv);

    const size_t GEMM_SMEM = (DIM * YT_STRIDE + DIM * DIM) * sizeof(float); // ~99 KB
    cudaFuncSetAttribute(gemmE_kernel, cudaFuncAttributeMaxDynamicSharedMemorySize,
                         (int)GEMM_SMEM);
    gemmE_kernel<<<(EE + 63) / 64, 256, GEMM_SMEM>>>(de, W);

    scatter3_kernel<<<blocks, 256>>>(rows, cols, dv, out);
}

// round 7
// speedup vs baseline: 1.9774x; 1.1572x over previous
#include <cuda_runtime.h>

#define NN   100000
#define EE   20000
#define NNZV 1000000
#define DIM  128

// ---- scratch: ~20.5 MB of device globals ----
__device__ float g_m[EE * DIM];    // 10.24 MB  hyperedge accumulator (de^-1, dv^-1/2 folded)
__device__ float g_m2[EE * DIM];   // 10.24 MB  m @ W

__device__ __forceinline__ void red4(float* p, float4 v) {
    asm volatile("red.global.add.v4.f32 [%0], {%1,%2,%3,%4};"
                 :: "l"(p), "f"(v.x), "f"(v.y), "f"(v.z), "f"(v.w) : "memory");
}

// ---- 1) zero m and out ----
__global__ void zero_kernel(float* __restrict__ out) {
    int tid = blockIdx.x * blockDim.x + threadIdx.x;
    int stride = gridDim.x * blockDim.x;
    float4* m4 = reinterpret_cast<float4*>(g_m);
    float4* o4 = reinterpret_cast<float4*>(out);
    const int M4 = EE * DIM / 4;
    const int O4 = NN * DIM / 4;
    float4 z = make_float4(0.f, 0.f, 0.f, 0.f);
    for (int i = tid; i < M4; i += stride) m4[i] = z;
    for (int i = tid; i < O4; i += stride) o4[i] = z;
}

// ---- 2) m[c] += (dv[r]^-1/2 / de[c]) * X[r]   — 4 entries per warp, MLP=4 ----
__global__ __launch_bounds__(256)
void scatter1_kernel(const float* __restrict__ X,
                     const int*   __restrict__ rows,
                     const int*   __restrict__ cols,
                     const float* __restrict__ dv,
                     const float* __restrict__ de) {
    int w = (blockIdx.x * blockDim.x + threadIdx.x) >> 5;
    int base = w * 4;
    if (base >= NNZV) return;
    int lane = threadIdx.x & 31;

    int r0 = __ldg(rows + base + 0), r1 = __ldg(rows + base + 1);
    int r2 = __ldg(rows + base + 2), r3 = __ldg(rows + base + 3);
    int c0 = __ldg(cols + base + 0), c1 = __ldg(cols + base + 1);
    int c2 = __ldg(cols + base + 2), c3 = __ldg(cols + base + 3);

    float s0 = rsqrtf(__ldg(dv + r0)) / __ldg(de + c0);
    float s1 = rsqrtf(__ldg(dv + r1)) / __ldg(de + c1);
    float s2 = rsqrtf(__ldg(dv + r2)) / __ldg(de + c2);
    float s3 = rsqrtf(__ldg(dv + r3)) / __ldg(de + c3);

    const float4* X4 = reinterpret_cast<const float4*>(X);
    float4 v0 = __ldg(X4 + r0 * (DIM / 4) + lane);
    float4 v1 = __ldg(X4 + r1 * (DIM / 4) + lane);
    float4 v2 = __ldg(X4 + r2 * (DIM / 4) + lane);
    float4 v3 = __ldg(X4 + r3 * (DIM / 4) + lane);

    v0.x *= s0; v0.y *= s0; v0.z *= s0; v0.w *= s0;
    v1.x *= s1; v1.y *= s1; v1.z *= s1; v1.w *= s1;
    v2.x *= s2; v2.y *= s2; v2.z *= s2; v2.w *= s2;
    v3.x *= s3; v3.y *= s3; v3.z *= s3; v3.w *= s3;

    red4(g_m + c0 * DIM + lane * 4, v0);
    red4(g_m + c1 * DIM + lane * 4, v1);
    red4(g_m + c2 * DIM + lane * 4, v2);
    red4(g_m + c3 * DIM + lane * 4, v3);
}

// ---- 3) M2 = m @ W    (E=20K rows; BM=64, 2 CTA/SM) ----
#define YT_STRIDE 68
__global__ __launch_bounds__(256, 2)
void gemmE_kernel(const float* __restrict__ W) {
    extern __shared__ float smem[];
    float* Yt = smem;                       // [DIM][YT_STRIDE] k-major
    float* Ws = smem + DIM * YT_STRIDE;     // [DIM][DIM] row-major

    int tid = threadIdx.x;
    int block_row = blockIdx.x * 64;

    for (int i = tid; i < DIM * (DIM / 4); i += 256) {
        int r = i >> 5, c4 = i & 31;
        float4 v = __ldg(reinterpret_cast<const float4*>(W) + r * (DIM / 4) + c4);
        *reinterpret_cast<float4*>(&Ws[r * DIM + c4 * 4]) = v;
    }
    for (int i = tid; i < (DIM / 4) * 64; i += 256) {
        int r = i & 63, c4 = i >> 6;
        int e = block_row + r;
        float4 v = make_float4(0.f, 0.f, 0.f, 0.f);
        if (e < EE)
            v = *(reinterpret_cast<const float4*>(g_m) + e * (DIM / 4) + c4);
        Yt[(c4 * 4 + 0) * YT_STRIDE + r] = v.x;
        Yt[(c4 * 4 + 1) * YT_STRIDE + r] = v.y;
        Yt[(c4 * 4 + 2) * YT_STRIDE + r] = v.z;
        Yt[(c4 * 4 + 3) * YT_STRIDE + r] = v.w;
    }
    __syncthreads();

    int tx = tid & 15;
    int ty = tid >> 4;

    float acc[4][8];
#pragma unroll
    for (int i = 0; i < 4; i++)
#pragma unroll
        for (int j = 0; j < 8; j++) acc[i][j] = 0.f;

#pragma unroll 4
    for (int k = 0; k < DIM; k++) {
        float yf[4], wf[8];
        *reinterpret_cast<float4*>(&yf[0]) = *reinterpret_cast<float4*>(&Yt[k * YT_STRIDE + ty * 4]);
        *reinterpret_cast<float4*>(&wf[0]) = *reinterpret_cast<float4*>(&Ws[k * DIM + tx * 8]);
        *reinterpret_cast<float4*>(&wf[4]) = *reinterpret_cast<float4*>(&Ws[k * DIM + tx * 8 + 4]);
#pragma unroll
        for (int i = 0; i < 4; i++)
#pragma unroll
            for (int j = 0; j < 8; j++)
                acc[i][j] += yf[i] * wf[j];
    }

#pragma unroll
    for (int i = 0; i < 4; i++) {
        int e = block_row + ty * 4 + i;
        if (e < EE) {
            float4 lo = make_float4(acc[i][0], acc[i][1], acc[i][2], acc[i][3]);
            float4 hi = make_float4(acc[i][4], acc[i][5], acc[i][6], acc[i][7]);
            *reinterpret_cast<float4*>(&g_m2[e * DIM + tx * 8])     = lo;
            *reinterpret_cast<float4*>(&g_m2[e * DIM + tx * 8 + 4]) = hi;
        }
    }
}

// ---- 4) out[r] += dv[r]^-1/2 * M2[c]   — 4 entries per warp, MLP=4 ----
__global__ __launch_bounds__(256)
void scatter3_kernel(const int*   __restrict__ rows,
                     const int*   __restrict__ cols,
                     const float* __restrict__ dv,
                     float*       __restrict__ out) {
    int w = (blockIdx.x * blockDim.x + threadIdx.x) >> 5;
    int base = w * 4;
    if (base >= NNZV) return;
    int lane = threadIdx.x & 31;

    int r0 = __ldg(rows + base + 0), r1 = __ldg(rows + base + 1);
    int r2 = __ldg(rows + base + 2), r3 = __ldg(rows + base + 3);
    int c0 = __ldg(cols + base + 0), c1 = __ldg(cols + base + 1);
    int c2 = __ldg(cols + base + 2), c3 = __ldg(cols + base + 3);

    float s0 = rsqrtf(__ldg(dv + r0));
    float s1 = rsqrtf(__ldg(dv + r1));
    float s2 = rsqrtf(__ldg(dv + r2));
    float s3 = rsqrtf(__ldg(dv + r3));

    const float4* M4 = reinterpret_cast<const float4*>(g_m2);
    float4 v0 = M4[c0 * (DIM / 4) + lane];
    float4 v1 = M4[c1 * (DIM / 4) + lane];
    float4 v2 = M4[c2 * (DIM / 4) + lane];
    float4 v3 = M4[c3 * (DIM / 4) + lane];

    v0.x *= s0; v0.y *= s0; v0.z *= s0; v0.w *= s0;
    v1.x *= s1; v1.y *= s1; v1.z *= s1; v1.w *= s1;
    v2.x *= s2; v2.y *= s2; v2.z *= s2; v2.w *= s2;
    v3.x *= s3; v3.y *= s3; v3.z *= s3; v3.w *= s3;

    red4(out + r0 * DIM + lane * 4, v0);
    red4(out + r1 * DIM + lane * 4, v1);
    red4(out + r2 * DIM + lane * 4, v2);
    red4(out + r3 * DIM + lane * 4, v3);
}

extern "C" void kernel_launch(void* const* d_in, const int* in_sizes, int n_in,
                              void* d_out, int out_size) {
    const float* X    = (const float*)d_in[0];
    const int*   rows = (const int*)  d_in[1];
    const int*   cols = (const int*)  d_in[2];
    const float* dv   = (const float*)d_in[3];
    const float* de   = (const float*)d_in[4];
    const float* W    = (const float*)d_in[5];
    float*       out  = (float*)d_out;

    zero_kernel<<<2048, 256>>>(out);

    // 4 entries per warp: NNZ/4 warps
    long long total_threads = (long long)(NNZV / 4) * 32;
    int blocks = (int)((total_threads + 255) / 256);
    scatter1_kernel<<<blocks, 256>>>(X, rows, cols, dv, de);

    const size_t GEMM_SMEM = (DIM * YT_STRIDE + DIM * DIM) * sizeof(float); // ~99 KB
    cudaFuncSetAttribute(gemmE_kernel, cudaFuncAttributeMaxDynamicSharedMemorySize,
                         (int)GEMM_SMEM);
    gemmE_kernel<<<(EE + 63) / 64, 256, GEMM_SMEM>>>(W);

    scatter3_kernel<<<blocks, 256>>>(rows, cols, dv, out);
}

// round 8
// speedup vs baseline: 2.6956x; 1.3632x over previous
#include <cuda_runtime.h>

#define NN   100000
#define EE   20000
#define NNZV 1000000
#define DIM  128

// ---- scratch: ~30.4 MB device globals ----
__device__ int   g_ecnt[EE];
__device__ int   g_ncnt[NN];
__device__ int   g_eoff[EE + 1];
__device__ int   g_noff[NN + 1];
__device__ int   g_ecur[EE];
__device__ int   g_ncur[NN];
__device__ int   g_pe[64];
__device__ int   g_pn[128];
__device__ int   g_erows[NNZV];     // CSR by edge: node idx per slot (4 MB)
__device__ int   g_ncols[NNZV];     // CSC by node: edge idx per slot (4 MB)
__device__ float g_m[EE * DIM];     // 10.24 MB
__device__ float g_m2[EE * DIM];    // 10.24 MB
__device__ float g_dvis[NN];        // dv^-1/2
__device__ float g_deinv[EE];       // de^-1

// ---- 1) zero counters + precompute scales ----
__global__ void init_kernel(const float* __restrict__ dv,
                            const float* __restrict__ de) {
    int tid = blockIdx.x * blockDim.x + threadIdx.x;
    int stride = gridDim.x * blockDim.x;
    for (int i = tid; i < NN; i += stride) {
        g_ncnt[i] = 0;
        g_dvis[i] = rsqrtf(__ldg(dv + i));
    }
    for (int i = tid; i < EE; i += stride) {
        g_ecnt[i] = 0;
        g_deinv[i] = 1.0f / __ldg(de + i);
    }
}

// ---- 2) histogram degrees ----
__global__ void count_kernel(const int* __restrict__ rows,
                             const int* __restrict__ cols) {
    int tid = blockIdx.x * blockDim.x + threadIdx.x;
    int stride = gridDim.x * blockDim.x;
    for (int i = tid; i < NNZV; i += stride) {
        atomicAdd(&g_ecnt[__ldg(cols + i)], 1);
        atomicAdd(&g_ncnt[__ldg(rows + i)], 1);
    }
}

// ---- 3) block scans (device-global refs only — host ptrs to __device__
//         symbols are invalid, that was the rounds-2..4 corruption) ----
__device__ __forceinline__ void block_scan_body(const int* cnt, int* off,
                                                int* partial, int len) {
    __shared__ int s[1024];
    int tid = threadIdx.x;
    int i = blockIdx.x * 1024 + tid;
    int v = (i < len) ? cnt[i] : 0;
    s[tid] = v;
    for (int d = 1; d < 1024; d <<= 1) {
        __syncthreads();
        int t = (tid >= d) ? s[tid - d] : 0;
        __syncthreads();
        s[tid] += t;
    }
    __syncthreads();
    if (i < len) off[i] = s[tid] - v;
    if (tid == 1023) partial[blockIdx.x] = s[1023];
}
__global__ void scanA_edges_kernel() { block_scan_body(g_ecnt, g_eoff, g_pe, EE); }
__global__ void scanA_nodes_kernel() { block_scan_body(g_ncnt, g_noff, g_pn, NN); }

__global__ void scanB_kernel(int nbe, int nbn) {
    if (threadIdx.x == 0) {
        int run = 0;
        for (int b = 0; b < nbe; b++) { int t = g_pe[b]; g_pe[b] = run; run += t; }
    }
    if (threadIdx.x == 1) {
        int run = 0;
        for (int b = 0; b < nbn; b++) { int t = g_pn[b]; g_pn[b] = run; run += t; }
    }
}

__global__ void scanC_kernel() {
    int tid = blockIdx.x * blockDim.x + threadIdx.x;
    int stride = gridDim.x * blockDim.x;
    for (int i = tid; i < EE; i += stride) {
        int o = g_eoff[i] + g_pe[i >> 10];
        g_eoff[i] = o;
        g_ecur[i] = o;
    }
    for (int i = tid; i < NN; i += stride) {
        int o = g_noff[i] + g_pn[i >> 10];
        g_noff[i] = o;
        g_ncur[i] = o;
    }
    if (tid == 0) { g_eoff[EE] = NNZV; g_noff[NN] = NNZV; }
}

__global__ void fill_kernel(const int* __restrict__ rows,
                            const int* __restrict__ cols) {
    int tid = blockIdx.x * blockDim.x + threadIdx.x;
    int stride = gridDim.x * blockDim.x;
    for (int i = tid; i < NNZV; i += stride) {
        int r = __ldg(rows + i);
        int c = __ldg(cols + i);
        int p = atomicAdd(&g_ecur[c], 1);
        g_erows[p] = r;
        int q = atomicAdd(&g_ncur[r], 1);
        g_ncols[q] = c;
    }
}

// ---- 7) phase1: m[e] = de^-1 * Σ_{r∈e} dv^-1/2[r] X[r]  (warp per edge) ----
__global__ __launch_bounds__(256)
void phase1_kernel(const float* __restrict__ X) {
    int e = (blockIdx.x * blockDim.x + threadIdx.x) >> 5;
    if (e >= EE) return;
    int lane = threadIdx.x & 31;
    const float4* X4 = reinterpret_cast<const float4*>(X);

    int i = g_eoff[e], end = g_eoff[e + 1];
    float4 acc = make_float4(0.f, 0.f, 0.f, 0.f);
    for (; i + 4 <= end; i += 4) {
        int r0 = g_erows[i],     r1 = g_erows[i + 1];
        int r2 = g_erows[i + 2], r3 = g_erows[i + 3];
        float s0 = g_dvis[r0], s1 = g_dvis[r1];
        float s2 = g_dvis[r2], s3 = g_dvis[r3];
        float4 v0 = X4[r0 * (DIM / 4) + lane];
        float4 v1 = X4[r1 * (DIM / 4) + lane];
        float4 v2 = X4[r2 * (DIM / 4) + lane];
        float4 v3 = X4[r3 * (DIM / 4) + lane];
        acc.x += s0 * v0.x + s1 * v1.x + s2 * v2.x + s3 * v3.x;
        acc.y += s0 * v0.y + s1 * v1.y + s2 * v2.y + s3 * v3.y;
        acc.z += s0 * v0.z + s1 * v1.z + s2 * v2.z + s3 * v3.z;
        acc.w += s0 * v0.w + s1 * v1.w + s2 * v2.w + s3 * v3.w;
    }
    for (; i < end; i++) {
        int r = g_erows[i];
        float s = g_dvis[r];
        float4 v = X4[r * (DIM / 4) + lane];
        acc.x += s * v.x; acc.y += s * v.y;
        acc.z += s * v.z; acc.w += s * v.w;
    }
    float d = g_deinv[e];
    acc.x *= d; acc.y *= d; acc.z *= d; acc.w *= d;
    *(reinterpret_cast<float4*>(g_m) + e * (DIM / 4) + lane) = acc;
}

// ---- 8) gemmE: M2 = m @ W  (BM=64, 2 CTA/SM; verified R6/R7) ----
#define YT_STRIDE 68
__global__ __launch_bounds__(256, 2)
void gemmE_kernel(const float* __restrict__ W) {
    extern __shared__ float smem[];
    float* Yt = smem;
    float* Ws = smem + DIM * YT_STRIDE;

    int tid = threadIdx.x;
    int block_row = blockIdx.x * 64;

    for (int i = tid; i < DIM * (DIM / 4); i += 256) {
        int r = i >> 5, c4 = i & 31;
        float4 v = __ldg(reinterpret_cast<const float4*>(W) + r * (DIM / 4) + c4);
        *reinterpret_cast<float4*>(&Ws[r * DIM + c4 * 4]) = v;
    }
    for (int i = tid; i < (DIM / 4) * 64; i += 256) {
        int r = i & 63, c4 = i >> 6;
        int e = block_row + r;
        float4 v = make_float4(0.f, 0.f, 0.f, 0.f);
        if (e < EE)
            v = *(reinterpret_cast<const float4*>(g_m) + e * (DIM / 4) + c4);
        Yt[(c4 * 4 + 0) * YT_STRIDE + r] = v.x;
        Yt[(c4 * 4 + 1) * YT_STRIDE + r] = v.y;
        Yt[(c4 * 4 + 2) * YT_STRIDE + r] = v.z;
        Yt[(c4 * 4 + 3) * YT_STRIDE + r] = v.w;
    }
    __syncthreads();

    int tx = tid & 15;
    int ty = tid >> 4;

    float acc[4][8];
#pragma unroll
    for (int i = 0; i < 4; i++)
#pragma unroll
        for (int j = 0; j < 8; j++) acc[i][j] = 0.f;

#pragma unroll 4
    for (int k = 0; k < DIM; k++) {
        float yf[4], wf[8];
        *reinterpret_cast<float4*>(&yf[0]) = *reinterpret_cast<float4*>(&Yt[k * YT_STRIDE + ty * 4]);
        *reinterpret_cast<float4*>(&wf[0]) = *reinterpret_cast<float4*>(&Ws[k * DIM + tx * 8]);
        *reinterpret_cast<float4*>(&wf[4]) = *reinterpret_cast<float4*>(&Ws[k * DIM + tx * 8 + 4]);
#pragma unroll
        for (int i = 0; i < 4; i++)
#pragma unroll
            for (int j = 0; j < 8; j++)
                acc[i][j] += yf[i] * wf[j];
    }

#pragma unroll
    for (int i = 0; i < 4; i++) {
        int e = block_row + ty * 4 + i;
        if (e < EE) {
            float4 lo = make_float4(acc[i][0], acc[i][1], acc[i][2], acc[i][3]);
            float4 hi = make_float4(acc[i][4], acc[i][5], acc[i][6], acc[i][7]);
            *reinterpret_cast<float4*>(&g_m2[e * DIM + tx * 8])     = lo;
            *reinterpret_cast<float4*>(&g_m2[e * DIM + tx * 8 + 4]) = hi;
        }
    }
}

// ---- 9) phase2: out[n] = dv^-1/2[n] * Σ_{e∋n} M2[e]  (warp per node) ----
__global__ __launch_bounds__(256)
void phase2_kernel(float* __restrict__ out) {
    int n = (blockIdx.x * blockDim.x + threadIdx.x) >> 5;
    if (n >= NN) return;
    int lane = threadIdx.x & 31;
    const float4* M4 = reinterpret_cast<const float4*>(g_m2);

    int i = g_noff[n], end = g_noff[n + 1];
    float4 acc = make_float4(0.f, 0.f, 0.f, 0.f);
    for (; i + 4 <= end; i += 4) {
        int c0 = g_ncols[i],     c1 = g_ncols[i + 1];
        int c2 = g_ncols[i + 2], c3 = g_ncols[i + 3];
        float4 v0 = M4[c0 * (DIM / 4) + lane];
        float4 v1 = M4[c1 * (DIM / 4) + lane];
        float4 v2 = M4[c2 * (DIM / 4) + lane];
        float4 v3 = M4[c3 * (DIM / 4) + lane];
        acc.x += (v0.x + v1.x) + (v2.x + v3.x);
        acc.y += (v0.y + v1.y) + (v2.y + v3.y);
        acc.z += (v0.z + v1.z) + (v2.z + v3.z);
        acc.w += (v0.w + v1.w) + (v2.w + v3.w);
    }
    for (; i < end; i++) {
        float4 v = M4[g_ncols[i] * (DIM / 4) + lane];
        acc.x += v.x; acc.y += v.y; acc.z += v.z; acc.w += v.w;
    }
    float s = g_dvis[n];
    acc.x *= s; acc.y *= s; acc.z *= s; acc.w *= s;
    *(reinterpret_cast<float4*>(out) + n * (DIM / 4) + lane) = acc;
}

extern "C" void kernel_launch(void* const* d_in, const int* in_sizes, int n_in,
                              void* d_out, int out_size) {
    const float* X    = (const float*)d_in[0];
    const int*   rows = (const int*)  d_in[1];
    const int*   cols = (const int*)  d_in[2];
    const float* dv   = (const float*)d_in[3];
    const float* de   = (const float*)d_in[4];
    const float* W    = (const float*)d_in[5];
    float*       out  = (float*)d_out;

    const int NBE = (EE + 1023) / 1024;   // 20
    const int NBN = (NN + 1023) / 1024;   // 98

    init_kernel<<<512, 256>>>(dv, de);
    count_kernel<<<2048, 256>>>(rows, cols);
    scanA_edges_kernel<<<NBE, 1024>>>();
    scanA_nodes_kernel<<<NBN, 1024>>>();
    scanB_kernel<<<1, 32>>>(NBE, NBN);
    scanC_kernel<<<512, 256>>>();
    fill_kernel<<<2048, 256>>>(rows, cols);

    phase1_kernel<<<(EE * 32 + 255) / 256, 256>>>(X);

    const size_t GEMM_SMEM = (DIM * YT_STRIDE + DIM * DIM) * sizeof(float);
    cudaFuncSetAttribute(gemmE_kernel, cudaFuncAttributeMaxDynamicSharedMemorySize,
                         (int)GEMM_SMEM);
    gemmE_kernel<<<(EE + 63) / 64, 256, GEMM_SMEM>>>(W);

    phase2_kernel<<<((long long)NN * 32 + 255) / 256, 256>>>(out);
}

// round 9
// speedup vs baseline: 2.8023x; 1.0396x over previous
#include <cuda_runtime.h>
#include <cuda_fp16.h>

#define NN   100000
#define EE   20000
#define NNZV 1000000
#define DIM  128

struct alignas(8) h4 { __half2 a, b; };

// ---- scratch: ~50 MB device globals ----
__device__ int    g_ecnt[EE];
__device__ int    g_ncnt[NN];
__device__ int    g_eoff[EE + 1];
__device__ int    g_noff[NN + 1];
__device__ int    g_ecur[EE];
__device__ int    g_ncur[NN];
__device__ int    g_pe[64];
__device__ int    g_pn[128];
__device__ int    g_erows[NNZV];      // CSR by edge: node idx per slot (4 MB)
__device__ int    g_ncols[NNZV];      // CSC by node: edge idx per slot (4 MB)
__device__ __half g_xh[NN * DIM];     // 25.6 MB  fp16(dv^-1/2 * X)
__device__ float  g_m[EE * DIM];      // 10.24 MB fp32 hyperedge features
__device__ __half g_m2h[EE * DIM];    // 5.12 MB  fp16 (m @ W)
__device__ float  g_dvis[NN];         // dv^-1/2
__device__ float  g_deinv[EE];        // de^-1

// ---- 1) zero counters + scales + X -> fp16 with dv^-1/2 folded ----
__global__ void init_kernel(const float* __restrict__ X,
                            const float* __restrict__ dv,
                            const float* __restrict__ de) {
    int tid = blockIdx.x * blockDim.x + threadIdx.x;
    int stride = gridDim.x * blockDim.x;
    for (int i = tid; i < NN; i += stride) {
        g_ncnt[i] = 0;
        g_dvis[i] = rsqrtf(__ldg(dv + i));
    }
    for (int i = tid; i < EE; i += stride) {
        g_ecnt[i] = 0;
        g_deinv[i] = 1.0f / __ldg(de + i);
    }
    const float4* X4 = reinterpret_cast<const float4*>(X);
    h4* Xh = reinterpret_cast<h4*>(g_xh);
    const int UNITS = NN * (DIM / 4);
    for (int u = tid; u < UNITS; u += stride) {
        int r = u >> 5;
        float s = rsqrtf(__ldg(dv + r));
        float4 x = __ldg(X4 + u);
        h4 o;
        o.a = __floats2half2_rn(s * x.x, s * x.y);
        o.b = __floats2half2_rn(s * x.z, s * x.w);
        Xh[u] = o;
    }
}

// ---- 2) histogram degrees ----
__global__ void count_kernel(const int* __restrict__ rows,
                             const int* __restrict__ cols) {
    int tid = blockIdx.x * blockDim.x + threadIdx.x;
    int stride = gridDim.x * blockDim.x;
    for (int i = tid; i < NNZV; i += stride) {
        atomicAdd(&g_ecnt[__ldg(cols + i)], 1);
        atomicAdd(&g_ncnt[__ldg(rows + i)], 1);
    }
}

// ---- 3) block scans (device-global refs only) ----
__device__ __forceinline__ void block_scan_body(const int* cnt, int* off,
                                                int* partial, int len) {
    __shared__ int s[1024];
    int tid = threadIdx.x;
    int i = blockIdx.x * 1024 + tid;
    int v = (i < len) ? cnt[i] : 0;
    s[tid] = v;
    for (int d = 1; d < 1024; d <<= 1) {
        __syncthreads();
        int t = (tid >= d) ? s[tid - d] : 0;
        __syncthreads();
        s[tid] += t;
    }
    __syncthreads();
    if (i < len) off[i] = s[tid] - v;
    if (tid == 1023) partial[blockIdx.x] = s[1023];
}
__global__ void scanA_edges_kernel() { block_scan_body(g_ecnt, g_eoff, g_pe, EE); }
__global__ void scanA_nodes_kernel() { block_scan_body(g_ncnt, g_noff, g_pn, NN); }

__global__ void scanB_kernel(int nbe, int nbn) {
    if (threadIdx.x == 0) {
        int run = 0;
        for (int b = 0; b < nbe; b++) { int t = g_pe[b]; g_pe[b] = run; run += t; }
    }
    if (threadIdx.x == 1) {
        int run = 0;
        for (int b = 0; b < nbn; b++) { int t = g_pn[b]; g_pn[b] = run; run += t; }
    }
}

__global__ void scanC_kernel() {
    int tid = blockIdx.x * blockDim.x + threadIdx.x;
    int stride = gridDim.x * blockDim.x;
    for (int i = tid; i < EE; i += stride) {
        int o = g_eoff[i] + g_pe[i >> 10];
        g_eoff[i] = o;
        g_ecur[i] = o;
    }
    for (int i = tid; i < NN; i += stride) {
        int o = g_noff[i] + g_pn[i >> 10];
        g_noff[i] = o;
        g_ncur[i] = o;
    }
    if (tid == 0) { g_eoff[EE] = NNZV; g_noff[NN] = NNZV; }
}

__global__ void fill_kernel(const int* __restrict__ rows,
                            const int* __restrict__ cols) {
    int tid = blockIdx.x * blockDim.x + threadIdx.x;
    int stride = gridDim.x * blockDim.x;
    for (int i = tid; i < NNZV; i += stride) {
        int r = __ldg(rows + i);
        int c = __ldg(cols + i);
        int p = atomicAdd(&g_ecur[c], 1);
        g_erows[p] = r;
        int q = atomicAdd(&g_ncur[r], 1);
        g_ncols[q] = c;
    }
}

// ---- 7) phase1: m[e] = de^-1 * Σ_{r∈e} Xh[r]  (warp per edge, fp16 gather) ----
__global__ __launch_bounds__(256)
void phase1_kernel() {
    int e = (blockIdx.x * blockDim.x + threadIdx.x) >> 5;
    if (e >= EE) return;
    int lane = threadIdx.x & 31;
    const h4* Xh = reinterpret_cast<const h4*>(g_xh);

    int i = g_eoff[e], end = g_eoff[e + 1];
    float4 acc = make_float4(0.f, 0.f, 0.f, 0.f);
    for (; i + 4 <= end; i += 4) {
        int r0 = g_erows[i],     r1 = g_erows[i + 1];
        int r2 = g_erows[i + 2], r3 = g_erows[i + 3];
        h4 v0 = Xh[r0 * 32 + lane];
        h4 v1 = Xh[r1 * 32 + lane];
        h4 v2 = Xh[r2 * 32 + lane];
        h4 v3 = Xh[r3 * 32 + lane];
        float2 a0 = __half22float2(v0.a), b0 = __half22float2(v0.b);
        float2 a1 = __half22float2(v1.a), b1 = __half22float2(v1.b);
        float2 a2 = __half22float2(v2.a), b2 = __half22float2(v2.b);
        float2 a3 = __half22float2(v3.a), b3 = __half22float2(v3.b);
        acc.x += (a0.x + a1.x) + (a2.x + a3.x);
        acc.y += (a0.y + a1.y) + (a2.y + a3.y);
        acc.z += (b0.x + b1.x) + (b2.x + b3.x);
        acc.w += (b0.y + b1.y) + (b2.y + b3.y);
    }
    for (; i < end; i++) {
        h4 v = Xh[g_erows[i] * 32 + lane];
        float2 a = __half22float2(v.a), b = __half22float2(v.b);
        acc.x += a.x; acc.y += a.y; acc.z += b.x; acc.w += b.y;
    }
    float d = g_deinv[e];
    acc.x *= d; acc.y *= d; acc.z *= d; acc.w *= d;
    *(reinterpret_cast<float4*>(g_m) + e * (DIM / 4) + lane) = acc;
}

// ---- 8) gemmE: M2h = fp16(m @ W)  (BM=64, 2 CTA/SM) ----
#define YT_STRIDE 68
__global__ __launch_bounds__(256, 2)
void gemmE_kernel(const float* __restrict__ W) {
    extern __shared__ float smem[];
    float* Yt = smem;
    float* Ws = smem + DIM * YT_STRIDE;

    int tid = threadIdx.x;
    int block_row = blockIdx.x * 64;

    for (int i = tid; i < DIM * (DIM / 4); i += 256) {
        int r = i >> 5, c4 = i & 31;
        float4 v = __ldg(reinterpret_cast<const float4*>(W) + r * (DIM / 4) + c4);
        *reinterpret_cast<float4*>(&Ws[r * DIM + c4 * 4]) = v;
    }
    for (int i = tid; i < (DIM / 4) * 64; i += 256) {
        int r = i & 63, c4 = i >> 6;
        int e = block_row + r;
        float4 v = make_float4(0.f, 0.f, 0.f, 0.f);
        if (e < EE)
            v = *(reinterpret_cast<const float4*>(g_m) + e * (DIM / 4) + c4);
        Yt[(c4 * 4 + 0) * YT_STRIDE + r] = v.x;
        Yt[(c4 * 4 + 1) * YT_STRIDE + r] = v.y;
        Yt[(c4 * 4 + 2) * YT_STRIDE + r] = v.z;
        Yt[(c4 * 4 + 3) * YT_STRIDE + r] = v.w;
    }
    __syncthreads();

    int tx = tid & 15;
    int ty = tid >> 4;

    float acc[4][8];
#pragma unroll
    for (int i = 0; i < 4; i++)
#pragma unroll
        for (int j = 0; j < 8; j++) acc[i][j] = 0.f;

#pragma unroll 4
    for (int k = 0; k < DIM; k++) {
        float yf[4], wf[8];
        *reinterpret_cast<float4*>(&yf[0]) = *reinterpret_cast<float4*>(&Yt[k * YT_STRIDE + ty * 4]);
        *reinterpret_cast<float4*>(&wf[0]) = *reinterpret_cast<float4*>(&Ws[k * DIM + tx * 8]);
        *reinterpret_cast<float4*>(&wf[4]) = *reinterpret_cast<float4*>(&Ws[k * DIM + tx * 8 + 4]);
#pragma unroll
        for (int i = 0; i < 4; i++)
#pragma unroll
            for (int j = 0; j < 8; j++)
                acc[i][j] += yf[i] * wf[j];
    }

#pragma unroll
    for (int i = 0; i < 4; i++) {
        int e = block_row + ty * 4 + i;
        if (e < EE) {
            alignas(16) __half2 hh[4];
            hh[0] = __floats2half2_rn(acc[i][0], acc[i][1]);
            hh[1] = __floats2half2_rn(acc[i][2], acc[i][3]);
            hh[2] = __floats2half2_rn(acc[i][4], acc[i][5]);
            hh[3] = __floats2half2_rn(acc[i][6], acc[i][7]);
            *reinterpret_cast<uint4*>(&g_m2h[e * DIM + tx * 8]) =
                *reinterpret_cast<uint4*>(hh);
        }
    }
}

// ---- 9) phase2: out[n] = dv^-1/2[n] * Σ_{e∋n} M2h[e]  (warp per node) ----
__global__ __launch_bounds__(256)
void phase2_kernel(float* __restrict__ out) {
    int n = (blockIdx.x * blockDim.x + threadIdx.x) >> 5;
    if (n >= NN) return;
    int lane = threadIdx.x & 31;
    const h4* M2 = reinterpret_cast<const h4*>(g_m2h);

    int i = g_noff[n], end = g_noff[n + 1];
    float4 acc = make_float4(0.f, 0.f, 0.f, 0.f);
    for (; i + 4 <= end; i += 4) {
        int c0 = g_ncols[i],     c1 = g_ncols[i + 1];
        int c2 = g_ncols[i + 2], c3 = g_ncols[i + 3];
        h4 v0 = M2[c0 * 32 + lane];
        h4 v1 = M2[c1 * 32 + lane];
        h4 v2 = M2[c2 * 32 + lane];
        h4 v3 = M2[c3 * 32 + lane];
        float2 a0 = __half22float2(v0.a), b0 = __half22float2(v0.b);
        float2 a1 = __half22float2(v1.a), b1 = __half22float2(v1.b);
        float2 a2 = __half22float2(v2.a), b2 = __half22float2(v2.b);
        float2 a3 = __half22float2(v3.a), b3 = __half22float2(v3.b);
        acc.x += (a0.x + a1.x) + (a2.x + a3.x);
        acc.y += (a0.y + a1.y) + (a2.y + a3.y);
        acc.z += (b0.x + b1.x) + (b2.x + b3.x);
        acc.w += (b0.y + b1.y) + (b2.y + b3.y);
    }
    for (; i < end; i++) {
        h4 v = M2[g_ncols[i] * 32 + lane];
        float2 a = __half22float2(v.a), b = __half22float2(v.b);
        acc.x += a.x; acc.y += a.y; acc.z += b.x; acc.w += b.y;
    }
    float s = g_dvis[n];
    acc.x *= s; acc.y *= s; acc.z *= s; acc.w *= s;
    *(reinterpret_cast<float4*>(out) + n * (DIM / 4) + lane) = acc;
}

extern "C" void kernel_launch(void* const* d_in, const int* in_sizes, int n_in,
                              void* d_out, int out_size) {
    const float* X    = (const float*)d_in[0];
    const int*   rows = (const int*)  d_in[1];
    const int*   cols = (const int*)  d_in[2];
    const float* dv   = (const float*)d_in[3];
    const float* de   = (const float*)d_in[4];
    const float* W    = (const float*)d_in[5];
    float*       out  = (float*)d_out;

    const int NBE = (EE + 1023) / 1024;   // 20
    const int NBN = (NN + 1023) / 1024;   // 98

    init_kernel<<<2048, 256>>>(X, dv, de);
    count_kernel<<<2048, 256>>>(rows, cols);
    scanA_edges_kernel<<<NBE, 1024>>>();
    scanA_nodes_kernel<<<NBN, 1024>>>();
    scanB_kernel<<<1, 32>>>(NBE, NBN);
    scanC_kernel<<<512, 256>>>();
    fill_kernel<<<2048, 256>>>(rows, cols);

    phase1_kernel<<<(EE * 32 + 255) / 256, 256>>>();

    const size_t GEMM_SMEM = (DIM * YT_STRIDE + DIM * DIM) * sizeof(float);
    cudaFuncSetAttribute(gemmE_kernel, cudaFuncAttributeMaxDynamicSharedMemorySize,
                         (int)GEMM_SMEM);
    gemmE_kernel<<<(EE + 63) / 64, 256, GEMM_SMEM>>>(W);

    phase2_kernel<<<((long long)NN * 32 + 255) / 256, 256>>>(out);
}

// round 10
// speedup vs baseline: 2.8869x; 1.0302x over previous
#include <cuda_runtime.h>
#include <cuda_fp16.h>

#define NN   100000
#define EE   20000
#define NNZV 1000000
#define DIM  128

struct alignas(8) h4 { __half2 a, b; };

// ---- scratch: ~50 MB device globals ----
__device__ int    g_ecnt[EE];
__device__ int    g_ncnt[NN];
__device__ int    g_eoff[EE + 1];
__device__ int    g_noff[NN + 1];
__device__ int    g_ecur[EE];
__device__ int    g_ncur[NN];
__device__ int    g_pe[64];
__device__ int    g_pn[128];
__device__ int    g_erows[NNZV];      // CSR by edge: node idx per slot (4 MB)
__device__ int    g_ncols[NNZV];      // CSC by node: edge idx per slot (4 MB)
__device__ __half g_xh[NN * DIM];     // 25.6 MB  fp16(dv^-1/2 * X)
__device__ float  g_m[EE * DIM];      // 10.24 MB fp32 hyperedge features
__device__ __half g_m2h[EE * DIM];    // 5.12 MB  fp16 (m @ W)
__device__ float  g_dvis[NN];         // dv^-1/2
__device__ float  g_deinv[EE];        // de^-1

// ---- 1) zero counters + scales + X -> fp16 with dv^-1/2 folded ----
__global__ void init_kernel(const float* __restrict__ X,
                            const float* __restrict__ dv,
                            const float* __restrict__ de) {
    int tid = blockIdx.x * blockDim.x + threadIdx.x;
    int stride = gridDim.x * blockDim.x;
    for (int i = tid; i < NN; i += stride) {
        g_ncnt[i] = 0;
        g_dvis[i] = rsqrtf(__ldg(dv + i));
    }
    for (int i = tid; i < EE; i += stride) {
        g_ecnt[i] = 0;
        g_deinv[i] = 1.0f / __ldg(de + i);
    }
    const float4* X4 = reinterpret_cast<const float4*>(X);
    h4* Xh = reinterpret_cast<h4*>(g_xh);
    const int UNITS = NN * (DIM / 4);
    for (int u = tid; u < UNITS; u += stride) {
        int r = u >> 5;
        float s = rsqrtf(__ldg(dv + r));
        float4 x = __ldg(X4 + u);
        h4 o;
        o.a = __floats2half2_rn(s * x.x, s * x.y);
        o.b = __floats2half2_rn(s * x.z, s * x.w);
        Xh[u] = o;
    }
}

// ---- 2) histogram degrees ----
__global__ void count_kernel(const int* __restrict__ rows,
                             const int* __restrict__ cols) {
    int tid = blockIdx.x * blockDim.x + threadIdx.x;
    int stride = gridDim.x * blockDim.x;
    for (int i = tid; i < NNZV; i += stride) {
        atomicAdd(&g_ecnt[__ldg(cols + i)], 1);
        atomicAdd(&g_ncnt[__ldg(rows + i)], 1);
    }
}

// ---- 3) block scans: warp-shuffle based (2 barriers, not 20) ----
__device__ __forceinline__ void block_scan_body(const int* cnt, int* off,
                                                int* partial, int len) {
    __shared__ int ws[32];
    int tid = threadIdx.x;
    int lane = tid & 31, wid = tid >> 5;
    int i = blockIdx.x * 1024 + tid;
    int v = (i < len) ? cnt[i] : 0;
    int sum = v;
#pragma unroll
    for (int d = 1; d < 32; d <<= 1) {
        int t = __shfl_up_sync(0xffffffffu, sum, d);
        if (lane >= d) sum += t;
    }
    if (lane == 31) ws[wid] = sum;
    __syncthreads();
    if (wid == 0) {
        int wsum = ws[lane];
#pragma unroll
        for (int d = 1; d < 32; d <<= 1) {
            int t = __shfl_up_sync(0xffffffffu, wsum, d);
            if (lane >= d) wsum += t;
        }
        ws[lane] = wsum;
    }
    __syncthreads();
    int incl = sum + (wid > 0 ? ws[wid - 1] : 0);
    if (i < len) off[i] = incl - v;
    if (tid == 1023) partial[blockIdx.x] = incl;
}
__global__ void scanA_edges_kernel() { block_scan_body(g_ecnt, g_eoff, g_pe, EE); }
__global__ void scanA_nodes_kernel() { block_scan_body(g_ncnt, g_noff, g_pn, NN); }

__global__ void scanB_kernel(int nbe, int nbn) {
    if (threadIdx.x == 0) {
        int run = 0;
        for (int b = 0; b < nbe; b++) { int t = g_pe[b]; g_pe[b] = run; run += t; }
    }
    if (threadIdx.x == 1) {
        int run = 0;
        for (int b = 0; b < nbn; b++) { int t = g_pn[b]; g_pn[b] = run; run += t; }
    }
}

__global__ void scanC_kernel() {
    int tid = blockIdx.x * blockDim.x + threadIdx.x;
    int stride = gridDim.x * blockDim.x;
    for (int i = tid; i < EE; i += stride) {
        int o = g_eoff[i] + g_pe[i >> 10];
        g_eoff[i] = o;
        g_ecur[i] = o;
    }
    for (int i = tid; i < NN; i += stride) {
        int o = g_noff[i] + g_pn[i >> 10];
        g_noff[i] = o;
        g_ncur[i] = o;
    }
    if (tid == 0) { g_eoff[EE] = NNZV; g_noff[NN] = NNZV; }
}

__global__ void fill_kernel(const int* __restrict__ rows,
                            const int* __restrict__ cols) {
    int tid = blockIdx.x * blockDim.x + threadIdx.x;
    int stride = gridDim.x * blockDim.x;
    for (int i = tid; i < NNZV; i += stride) {
        int r = __ldg(rows + i);
        int c = __ldg(cols + i);
        int p = atomicAdd(&g_ecur[c], 1);
        g_erows[p] = r;
        int q = atomicAdd(&g_ncur[r], 1);
        g_ncols[q] = c;
    }
}

// ---- 7) phase1: m[e] = de^-1 * Σ_{r∈e} Xh[r]  (warp/edge, fp16, MLP=8) ----
__global__ __launch_bounds__(256)
void phase1_kernel() {
    int e = (blockIdx.x * blockDim.x + threadIdx.x) >> 5;
    if (e >= EE) return;
    int lane = threadIdx.x & 31;
    const h4* Xh = reinterpret_cast<const h4*>(g_xh);

    int i = g_eoff[e], end = g_eoff[e + 1];
    float4 acc = make_float4(0.f, 0.f, 0.f, 0.f);
    for (; i + 8 <= end; i += 8) {
        int r[8];
#pragma unroll
        for (int u = 0; u < 8; u++) r[u] = g_erows[i + u];
        h4 v[8];
#pragma unroll
        for (int u = 0; u < 8; u++) v[u] = Xh[r[u] * 32 + lane];
#pragma unroll
        for (int u = 0; u < 8; u++) {
            float2 a = __half22float2(v[u].a), b = __half22float2(v[u].b);
            acc.x += a.x; acc.y += a.y; acc.z += b.x; acc.w += b.y;
        }
    }
    for (; i < end; i++) {
        h4 v = Xh[g_erows[i] * 32 + lane];
        float2 a = __half22float2(v.a), b = __half22float2(v.b);
        acc.x += a.x; acc.y += a.y; acc.z += b.x; acc.w += b.y;
    }
    float d = g_deinv[e];
    acc.x *= d; acc.y *= d; acc.z *= d; acc.w *= d;
    *(reinterpret_cast<float4*>(g_m) + e * (DIM / 4) + lane) = acc;
}

// ---- 8) gemmE: M2h = fp16(m @ W)  BM=128, 8x8 micro (R1-proven shape) ----
__global__ __launch_bounds__(256, 1)
void gemmE_kernel(const float* __restrict__ W) {
    extern __shared__ float smem[];
    float* Yt = smem;                 // [DIM][DIM] k-major: Yt[k*DIM + r]
    float* Ws = smem + DIM * DIM;     // [DIM][DIM] row-major

    int tid = threadIdx.x;
    int block_row = blockIdx.x * 128;

    for (int i = tid; i < DIM * (DIM / 4); i += 256) {
        int r = i >> 5, c4 = i & 31;
        float4 v = __ldg(reinterpret_cast<const float4*>(W) + r * (DIM / 4) + c4);
        *reinterpret_cast<float4*>(&Ws[r * DIM + c4 * 4]) = v;
    }
    for (int i = tid; i < (DIM / 4) * DIM; i += 256) {
        int r = i & 127, c4 = i >> 7;
        int e = block_row + r;
        float4 v = make_float4(0.f, 0.f, 0.f, 0.f);
        if (e < EE)
            v = *(reinterpret_cast<const float4*>(g_m) + e * (DIM / 4) + c4);
        Yt[(c4 * 4 + 0) * DIM + r] = v.x;
        Yt[(c4 * 4 + 1) * DIM + r] = v.y;
        Yt[(c4 * 4 + 2) * DIM + r] = v.z;
        Yt[(c4 * 4 + 3) * DIM + r] = v.w;
    }
    __syncthreads();

    int tx = tid & 15;   // 8 output cols
    int ty = tid >> 4;   // 8 output rows

    float acc[8][8];
#pragma unroll
    for (int i = 0; i < 8; i++)
#pragma unroll
        for (int j = 0; j < 8; j++) acc[i][j] = 0.f;

#pragma unroll 4
    for (int k = 0; k < DIM; k++) {
        float yf[8], wf[8];
        *reinterpret_cast<float4*>(&yf[0]) = *reinterpret_cast<float4*>(&Yt[k * DIM + ty * 8]);
        *reinterpret_cast<float4*>(&yf[4]) = *reinterpret_cast<float4*>(&Yt[k * DIM + ty * 8 + 4]);
        *reinterpret_cast<float4*>(&wf[0]) = *reinterpret_cast<float4*>(&Ws[k * DIM + tx * 8]);
        *reinterpret_cast<float4*>(&wf[4]) = *reinterpret_cast<float4*>(&Ws[k * DIM + tx * 8 + 4]);
#pragma unroll
        for (int i = 0; i < 8; i++)
#pragma unroll
            for (int j = 0; j < 8; j++)
                acc[i][j] += yf[i] * wf[j];
    }

#pragma unroll
    for (int i = 0; i < 8; i++) {
        int e = block_row + ty * 8 + i;
        if (e < EE) {
            alignas(16) __half2 hh[4];
            hh[0] = __floats2half2_rn(acc[i][0], acc[i][1]);
            hh[1] = __floats2half2_rn(acc[i][2], acc[i][3]);
            hh[2] = __floats2half2_rn(acc[i][4], acc[i][5]);
            hh[3] = __floats2half2_rn(acc[i][6], acc[i][7]);
            *reinterpret_cast<uint4*>(&g_m2h[e * DIM + tx * 8]) =
                *reinterpret_cast<uint4*>(hh);
        }
    }
}

// ---- 9) phase2: out[n] = dv^-1/2[n] * Σ_{e∋n} M2h[e]  (warp/node, MLP=8) ----
__global__ __launch_bounds__(256)
void phase2_kernel(float* __restrict__ out) {
    int n = (blockIdx.x * blockDim.x + threadIdx.x) >> 5;
    if (n >= NN) return;
    int lane = threadIdx.x & 31;
    const h4* M2 = reinterpret_cast<const h4*>(g_m2h);

    int i = g_noff[n], end = g_noff[n + 1];
    float4 acc = make_float4(0.f, 0.f, 0.f, 0.f);
    for (; i + 8 <= end; i += 8) {
        int c[8];
#pragma unroll
        for (int u = 0; u < 8; u++) c[u] = g_ncols[i + u];
        h4 v[8];
#pragma unroll
        for (int u = 0; u < 8; u++) v[u] = M2[c[u] * 32 + lane];
#pragma unroll
        for (int u = 0; u < 8; u++) {
            float2 a = __half22float2(v[u].a), b = __half22float2(v[u].b);
            acc.x += a.x; acc.y += a.y; acc.z += b.x; acc.w += b.y;
        }
    }
    for (; i < end; i++) {
        h4 v = M2[g_ncols[i] * 32 + lane];
        float2 a = __half22float2(v.a), b = __half22float2(v.b);
        acc.x += a.x; acc.y += a.y; acc.z += b.x; acc.w += b.y;
    }
    float s = g_dvis[n];
    acc.x *= s; acc.y *= s; acc.z *= s; acc.w *= s;
    *(reinterpret_cast<float4*>(out) + n * (DIM / 4) + lane) = acc;
}

extern "C" void kernel_launch(void* const* d_in, const int* in_sizes, int n_in,
                              void* d_out, int out_size) {
    const float* X    = (const float*)d_in[0];
    const int*   rows = (const int*)  d_in[1];
    const int*   cols = (const int*)  d_in[2];
    const float* dv   = (const float*)d_in[3];
    const float* de   = (const float*)d_in[4];
    const float* W    = (const float*)d_in[5];
    float*       out  = (float*)d_out;

    const int NBE = (EE + 1023) / 1024;   // 20
    const int NBN = (NN + 1023) / 1024;   // 98

    init_kernel<<<2048, 256>>>(X, dv, de);
    count_kernel<<<2048, 256>>>(rows, cols);
    scanA_edges_kernel<<<NBE, 1024>>>();
    scanA_nodes_kernel<<<NBN, 1024>>>();
    scanB_kernel<<<1, 32>>>(NBE, NBN);
    scanC_kernel<<<512, 256>>>();
    fill_kernel<<<2048, 256>>>(rows, cols);

    phase1_kernel<<<(EE * 32 + 255) / 256, 256>>>();

    const size_t GEMM_SMEM = 2 * DIM * DIM * sizeof(float);  // 128 KB
    cudaFuncSetAttribute(gemmE_kernel, cudaFuncAttributeMaxDynamicSharedMemorySize,
                         (int)GEMM_SMEM);
    gemmE_kernel<<<(EE + 127) / 128, 256, GEMM_SMEM>>>(W);

    phase2_kernel<<<((long long)NN * 32 + 255) / 256, 256>>>(out);
}